// round 14
// baseline (speedup 1.0000x reference)
#include <cuda_runtime.h>
#include <cuda_bf16.h>
#include <cstdint>
#include <cstddef>

#define NB   1024
#define NM   14
#define NBLK 148
#define WPB  7                  // warps (=buckets) per block
#define NTHR (WPB * 32)         // 224
#define NTOT (NBLK * NTHR)      // 33152

// Inflow ping-pong buffers + barrier state. Self-resetting per launch:
// zeros at start, consumer-zeroed per layer; arrive flags use monotonic
// phase numbers and are zeroed by the last-exiting block.
__device__ float    g_inflow[2][NB];
__device__ unsigned g_arrive[NBLK];
__device__ unsigned g_exit;

__device__ __forceinline__ float sqrt_approx(float x) {
    float y; asm("sqrt.approx.f32 %0, %1;" : "=f"(y) : "f"(x)); return y;
}
__device__ __forceinline__ unsigned ld_acq(const unsigned* p) {
    unsigned v; asm volatile("ld.acquire.gpu.global.u32 %0, [%1];" : "=r"(v) : "l"(p)); return v;
}
__device__ __forceinline__ void st_rel(unsigned* p, unsigned v) {
    asm volatile("st.release.gpu.global.u32 [%0], %1;" :: "l"(p), "r"(v) : "memory");
}
__device__ __forceinline__ void l2pf(const void* p) {
    asm volatile("prefetch.global.L2 [%0];" :: "l"(p));
}

// Grid barrier, contention-free arrivals: each block release-stores its
// phase into its own slot (no atomic serialization: 148 independent stores
// across 5 lines), and every block's warp 0 scans all 148 flags itself
// (5 independent acquire-loads per lane + ballot). Monotonic phases.
// release->acquire chain makes all pre-barrier writes (incl. REDs) visible.
__device__ __forceinline__ void grid_barrier(unsigned p) {
    __syncthreads();
    if (threadIdx.x < 32) {
        if (threadIdx.x == 0) {
            __threadfence();                 // order block's writes (cta->gpu)
            st_rel(&g_arrive[blockIdx.x], p);
        }
        const int lane = threadIdx.x;
        bool pending;
        do {
            bool ok = true;
            #pragma unroll
            for (int k = 0; k < 5; ++k) {
                int s = lane + k * 32;       // 0..159
                if (s < NBLK) ok &= (ld_acq(&g_arrive[s]) >= p);
            }
            pending = __ballot_sync(0xFFFFFFFFu, !ok) != 0u;
        } while (pending);
    }
    __syncthreads();
}

// Prefetch one mid layer (8 MB S + 4 MB theta = 98304 x 128B lines) into L2.
__device__ __forceinline__ void prefetch_layer(const char* Sb, const char* Tb,
                                               int l, int t) {
    const char* S = Sb + (size_t)l * 8388608;
    const char* T = Tb + (size_t)l * 4194304;
    #pragma unroll
    for (int k = 0; k < 3; ++k) {
        long line = (long)t + (long)k * NTOT;
        if (line < 65536)       l2pf(S + line * 128);
        else if (line < 98304)  l2pf(T + (line - 65536) * 128);
    }
}

// Stage a bucket row into registers: lane holds spigots {w*32+lane}.
__device__ __forceinline__ void stage_regs(const float2* __restrict__ S2,
                                           const float* __restrict__ T,
                                           int lane, float bh[32], float cc[32]) {
    const float SQ2G = 4.4271887242357310f;   // sqrt(2*9.8)
    #pragma unroll
    for (int w = 0; w < 32; ++w) {
        float2 p = S2[w * 32 + lane];
        bh[w] = p.x; cc[w] = p.y;
    }
    #pragma unroll
    for (int w = 0; w < 32; ++w)
        cc[w] = cc[w] * T[w * 32 + lane] * SQ2G;
}

// Sequential recurrence, H_eff-only form (see R13). Exact: dry spigots give
// q==0 and leave H_eff bit-identical; lowest firing index first via
// ballot+ffs; windows drain in index order. Early-exit (a) + eligibility
// bitmap (b) are exact under monotone-decreasing H.
// Returns final H_eff; cum = 2*(H0 - H_eff_final).
template <bool ATOMIC, bool EXTRACT>
__device__ float bucket_chain(int lane, float H0, float inflow,
                              const float bh[32], const float cc[32],
                              float* __restrict__ nxt,
                              int wb, int lb, float& qsel)
{
    const unsigned FULL = 0xFFFFFFFFu;
    // spigot 0: H_eff = H0 + inflow (reference quirk)
    float bh0 = __shfl_sync(FULL, bh[0], 0);
    float cc0 = __shfl_sync(FULL, cc[0], 0);
    float h0  = fmaxf((H0 + inflow) - bh0, 0.0f);
    float q0  = cc0 * sqrt_approx(h0);
    float H_eff = fmaf(-0.5f, q0, H0);

    float qx = 0.0f;

    // ---- window 0: plain loop (the H plunge happens here) ----
    {
        float qacc = (lane == 0) ? q0 : 0.0f;
        unsigned rem = 0xFFFFFFFEu;                      // spigot 0 done
        while (true) {
            float h = H_eff - bh[0];
            unsigned fire = __ballot_sync(FULL, h > 0.0f) & rem;
            if (!fire) break;
            float q  = cc[0] * sqrt_approx(h);
            float Hc = fmaf(-0.5f, q, H_eff);
            int f = __ffs(fire) - 1;
            H_eff = __shfl_sync(FULL, Hc, f);
            qacc = (lane == f) ? q : qacc;
            rem &= (0xFFFFFFFEu << f);
            if (!(fire & rem)) break;                    // exact early exit
        }
        if (EXTRACT) {
            qx = (wb == 0) ? qacc : qx;
        } else if (qacc != 0.0f) {
            if (ATOMIC) atomicAdd(&nxt[lane], qacc);
            else        nxt[lane] = qacc;
        }
    }

    // ---- eligibility bitmap for windows 1..31 (pipelined ballots) ----
    unsigned elig = 0u;
    #pragma unroll
    for (int w = 1; w < 32; ++w) {
        unsigned m = __ballot_sync(FULL, H_eff > bh[w]);
        elig |= (m ? 1u : 0u) << w;
    }

    #pragma unroll
    for (int w = 1; w < 32; ++w) {
        if (!(elig & (1u << w))) continue;               // never-eligible: 2cy
        float qacc = 0.0f;
        unsigned rem = FULL;
        while (true) {
            float h = H_eff - bh[w];
            unsigned fire = __ballot_sync(FULL, h > 0.0f) & rem;
            if (!fire) break;
            float q  = cc[w] * sqrt_approx(h);
            float Hc = fmaf(-0.5f, q, H_eff);
            int f = __ffs(fire) - 1;
            H_eff = __shfl_sync(FULL, Hc, f);
            qacc = (lane == f) ? q : qacc;
            rem &= (0xFFFFFFFEu << f);
            if (!(fire & rem)) break;                    // exact early exit
        }
        if (EXTRACT) {
            qx = (w == wb) ? qacc : qx;
        } else if (qacc != 0.0f) {
            if (ATOMIC) atomicAdd(&nxt[w * 32 + lane], qacc);
            else        nxt[w * 32 + lane] = qacc;
        }
    }
    if (EXTRACT) qsel = __shfl_sync(FULL, qx, lb);
    return H_eff;
}

// ---------------------------------------------------------------------------
// Persistent kernel: 148 blocks x 224 threads, 1 block/SM, register-resident
// chains. Head bucket solved redundantly by every warp (q0 from registers ->
// no extra phase). DRAM streams 2 layers ahead via bounded L2 prefetch.
// ---------------------------------------------------------------------------
__global__ void __launch_bounds__(NTHR, 1)
k_cascade(const float* __restrict__ H0p,   const float* __restrict__ H_mid,
          const float* __restrict__ H_last,const float* __restrict__ S0,
          const float* __restrict__ S_mid, const float* __restrict__ S_last,
          const float* __restrict__ theta0,const float* __restrict__ theta_mid,
          const float* __restrict__ theta_last, const float* __restrict__ precip,
          float* __restrict__ out)
{
    const int tid  = threadIdx.x;
    const int lane = tid & 31;
    const int w    = tid >> 5;                    // 0..6
    const int b    = blockIdx.x * WPB + w;        // bucket id (may be >= NB)
    const int t    = blockIdx.x * NTHR + tid;     // linear thread id

    // start the DRAM stream for layers 0 and 1 immediately
    prefetch_layer((const char*)S_mid, (const char*)theta_mid, 0, t);
    prefetch_layer((const char*)S_mid, (const char*)theta_mid, 1, t);

    if (lane == 0 && b < NB) { g_inflow[0][b] = 0.0f; g_inflow[1][b] = 0.0f; }

    const float pre      = precip[0];
    const float p_layer  = pre * (1.0f / 16.0f);
    const float p_bucket = p_layer * (1.0f / 1024.0f);

    float bh[32], cc[32];
    float q0_mine = 0.0f;
    float unused;

    // redundant head-bucket solve (identical data+ops on every warp)
    {
        stage_regs((const float2*)S0, theta0, lane, bh, cc);
        float H0h = H0p[0];
        float He = bucket_chain<false, true>(lane, H0h, p_layer, bh, cc,
                                             nullptr, (b & 1023) >> 5, b & 31,
                                             q0_mine);
        if (blockIdx.x == 0 && w == 0 && lane == 0)
            out[0] = (2.0f * He - H0h) + p_layer;    // H0 - cum + inflow
    }

    // stage layer 0 (prefetched above -> mostly L2 hits)
    if (b < NB)
        stage_regs((const float2*)S_mid + (size_t)b * NB,
                   theta_mid + (size_t)b * NB, lane, bh, cc);

    unsigned phase = 1;
    grid_barrier(phase); ++phase;                 // inflow zeros visible

    float inflow = q0_mine + p_bucket;            // layer-0 inflow from regs

    for (int l = 0; l < NM; ++l) {
        // layer l accumulates into buf[(l+1)&1]
        if (b < NB) {
            float H0 = H_mid[(size_t)l * NB + b];
            float He = bucket_chain<true, false>(lane, H0, inflow, bh, cc,
                                                 g_inflow[(l + 1) & 1], 0, 0,
                                                 unused);
            if (lane == 0) out[1 + l * NB + b] = (2.0f * He - H0) + inflow;
        }
        // stage l+1 (L2 hits) then keep the DRAM stream 2 layers ahead
        if (l + 1 < NM && b < NB) {
            size_t row = (size_t)(l + 1) * NB + (size_t)b;
            stage_regs((const float2*)S_mid + row * NB,
                       theta_mid + row * NB, lane, bh, cc);
        }
        if (l + 2 < NM)
            prefetch_layer((const char*)S_mid, (const char*)theta_mid, l + 2, t);

        grid_barrier(phase); ++phase;             // layer-l atomics visible

        // read next inflow (published by the barrier), zero slot for reuse
        if (l + 1 < NM && b < NB) {
            float inf0 = 0.0f;
            if (lane == 0) {
                inf0 = g_inflow[(l + 1) & 1][b];
                g_inflow[(l + 1) & 1][b] = 0.0f;
            }
            inflow = __shfl_sync(0xFFFFFFFFu, inf0, 0) + p_bucket;
        }
    }

    // last layer: one outlet spigot per bucket; layer 13 wrote buf[0]
    if (b < NB && lane == 0) {
        float inflowL = g_inflow[0][b] + p_bucket;
        float H0 = H_last[b];
        float sh = S_last[2 * b + 0];
        float a  = S_last[2 * b + 1];
        float h  = fmaxf((H0 + inflowL) - sh, 0.0f);
        float q  = theta_last[b] * sqrt_approx(19.6f * h) * a;
        out[1 + NM * NB + b]      = (H0 - q) + inflowL;
        out[1 + NM * NB + NB + b] = q;
    }

    // reset barrier state for the next graph replay (last block to exit;
    // all other blocks have passed their final barrier and no longer read it)
    __syncthreads();
    if (tid == 0) {
        __threadfence();
        unsigned v = atomicAdd(&g_exit, 1u);
        if (v == NBLK - 1) {
            for (int i = 0; i < NBLK; ++i) g_arrive[i] = 0u;
            g_exit = 0u;
            __threadfence();
        }
    }
}

// ---------------------------------------------------------------------------
extern "C" void kernel_launch(void* const* d_in, const int* in_sizes, int n_in,
                              void* d_out, int out_size)
{
    const float* H0         = (const float*)d_in[0];
    const float* H_mid      = (const float*)d_in[1];
    const float* H_last     = (const float*)d_in[2];
    const float* S0         = (const float*)d_in[3];
    const float* S_mid      = (const float*)d_in[4];
    const float* S_last     = (const float*)d_in[5];
    const float* theta0     = (const float*)d_in[6];
    const float* theta_mid  = (const float*)d_in[7];
    const float* theta_last = (const float*)d_in[8];
    const float* precip     = (const float*)d_in[9];
    float* out = (float*)d_out;

    k_cascade<<<NBLK, NTHR>>>(H0, H_mid, H_last, S0, S_mid, S_last,
                              theta0, theta_mid, theta_last, precip, out);
}

// round 15
// speedup vs baseline: 1.2723x; 1.2723x over previous
#include <cuda_runtime.h>
#include <cuda_bf16.h>
#include <cstdint>
#include <cstddef>

#define NB   1024
#define NM   14
#define NBLK 148
#define WPB  7                  // warps (=buckets) per block
#define NTHR (WPB * 32)         // 224
#define NTOT (NBLK * NTHR)      // 33152

// Inflow ping-pong buffers + dataflow counter. Self-resetting per launch:
// inflow slots zeroed at start / consumer-zeroed per layer; g_ctr/g_exit
// reset by the last-exiting block so graph replays start clean.
__device__ float    g_inflow[2][NB];
__device__ unsigned g_ctr;              // monotonic arrivals: 1024 per round
__device__ unsigned g_exit;

__device__ __forceinline__ float sqrt_approx(float x) {
    float y; asm("sqrt.approx.f32 %0, %1;" : "=f"(y) : "f"(x)); return y;
}
__device__ __forceinline__ unsigned ld_acq(const unsigned* p) {
    unsigned v; asm volatile("ld.acquire.gpu.global.u32 %0, [%1];" : "=r"(v) : "l"(p)); return v;
}
__device__ __forceinline__ void red_add_rel(unsigned* p, unsigned v) {
    asm volatile("red.release.gpu.global.add.u32 [%0], %1;" :: "l"(p), "r"(v) : "memory");
}
__device__ __forceinline__ void l2pf(const void* p) {
    asm volatile("prefetch.global.L2 [%0];" :: "l"(p));
}

// Prefetch one mid layer (8 MB S + 4 MB theta = 98304 x 128B lines) into L2.
__device__ __forceinline__ void prefetch_layer(const char* Sb, const char* Tb,
                                               int l, int t) {
    const char* S = Sb + (size_t)l * 8388608;
    const char* T = Tb + (size_t)l * 4194304;
    #pragma unroll
    for (int k = 0; k < 3; ++k) {
        long line = (long)t + (long)k * NTOT;
        if (line < 65536)       l2pf(S + line * 128);
        else if (line < 98304)  l2pf(T + (line - 65536) * 128);
    }
}

// Stage a bucket row into registers: lane holds spigots {w*32+lane}.
__device__ __forceinline__ void stage_regs(const float2* __restrict__ S2,
                                           const float* __restrict__ T,
                                           int lane, float bh[32], float cc[32]) {
    const float SQ2G = 4.4271887242357310f;   // sqrt(2*9.8)
    #pragma unroll
    for (int w = 0; w < 32; ++w) {
        float2 p = S2[w * 32 + lane];
        bh[w] = p.x; cc[w] = p.y;
    }
    #pragma unroll
    for (int w = 0; w < 32; ++w)
        cc[w] = cc[w] * T[w * 32 + lane] * SQ2G;
}

// Sequential recurrence, H_eff-only form (R13). Exact: dry spigots give
// q==0 and leave H_eff bit-identical; lowest firing index first via
// ballot+ffs; windows drain in index order. Early-exit + eligibility
// bitmap are exact under monotone-decreasing H.
// Returns final H_eff; cum = 2*(H0 - H_eff_final).
template <bool ATOMIC, bool EXTRACT>
__device__ float bucket_chain(int lane, float H0, float inflow,
                              const float bh[32], const float cc[32],
                              float* __restrict__ nxt,
                              int wb, int lb, float& qsel)
{
    const unsigned FULL = 0xFFFFFFFFu;
    // spigot 0: H_eff = H0 + inflow (reference quirk)
    float bh0 = __shfl_sync(FULL, bh[0], 0);
    float cc0 = __shfl_sync(FULL, cc[0], 0);
    float h0  = fmaxf((H0 + inflow) - bh0, 0.0f);
    float q0  = cc0 * sqrt_approx(h0);
    float H_eff = fmaf(-0.5f, q0, H0);

    float qx = 0.0f;

    // ---- window 0: plain loop (the H plunge happens here) ----
    {
        float qacc = (lane == 0) ? q0 : 0.0f;
        unsigned rem = 0xFFFFFFFEu;                      // spigot 0 done
        while (true) {
            float h = H_eff - bh[0];
            unsigned fire = __ballot_sync(FULL, h > 0.0f) & rem;
            if (!fire) break;
            float q  = cc[0] * sqrt_approx(h);
            float Hc = fmaf(-0.5f, q, H_eff);
            int f = __ffs(fire) - 1;
            H_eff = __shfl_sync(FULL, Hc, f);
            qacc = (lane == f) ? q : qacc;
            rem &= (0xFFFFFFFEu << f);
            if (!(fire & rem)) break;                    // exact early exit
        }
        if (EXTRACT) {
            qx = (wb == 0) ? qacc : qx;
        } else if (qacc != 0.0f) {
            if (ATOMIC) atomicAdd(&nxt[lane], qacc);
            else        nxt[lane] = qacc;
        }
    }

    // ---- eligibility bitmap for windows 1..31 (pipelined ballots) ----
    unsigned elig = 0u;
    #pragma unroll
    for (int w = 1; w < 32; ++w) {
        unsigned m = __ballot_sync(FULL, H_eff > bh[w]);
        elig |= (m ? 1u : 0u) << w;
    }

    #pragma unroll
    for (int w = 1; w < 32; ++w) {
        if (!(elig & (1u << w))) continue;               // never-eligible: 2cy
        float qacc = 0.0f;
        unsigned rem = FULL;
        while (true) {
            float h = H_eff - bh[w];
            unsigned fire = __ballot_sync(FULL, h > 0.0f) & rem;
            if (!fire) break;
            float q  = cc[w] * sqrt_approx(h);
            float Hc = fmaf(-0.5f, q, H_eff);
            int f = __ffs(fire) - 1;
            H_eff = __shfl_sync(FULL, Hc, f);
            qacc = (lane == f) ? q : qacc;
            rem &= (0xFFFFFFFEu << f);
            if (!(fire & rem)) break;                    // exact early exit
        }
        if (EXTRACT) {
            qx = (w == wb) ? qacc : qx;
        } else if (qacc != 0.0f) {
            if (ATOMIC) atomicAdd(&nxt[w * 32 + lane], qacc);
            else        nxt[w * 32 + lane] = qacc;
        }
    }
    if (EXTRACT) qsel = __shfl_sync(FULL, qx, lb);
    return H_eff;
}

// ---------------------------------------------------------------------------
// Persistent kernel: 148 blocks x 224 threads, 1 block/SM, register-resident
// chains. NO grid barrier: per-warp dataflow sync on one monotonic counter.
// Round k complete when g_ctr >= 1024*k (init zeros = round 1). Each warp:
// chain+flush -> fence -> release-arrive -> acquire-poll -> acquire-read
// inflow -> zero slot. Warps never wait on block siblings.
// ---------------------------------------------------------------------------
__global__ void __launch_bounds__(NTHR, 1)
k_cascade(const float* __restrict__ H0p,   const float* __restrict__ H_mid,
          const float* __restrict__ H_last,const float* __restrict__ S0,
          const float* __restrict__ S_mid, const float* __restrict__ S_last,
          const float* __restrict__ theta0,const float* __restrict__ theta_mid,
          const float* __restrict__ theta_last, const float* __restrict__ precip,
          float* __restrict__ out)
{
    const int tid  = threadIdx.x;
    const int lane = tid & 31;
    const int w    = tid >> 5;                    // 0..6
    const int b    = blockIdx.x * WPB + w;        // bucket id (may be >= NB)
    const int t    = blockIdx.x * NTHR + tid;     // linear thread id
    const bool act = (b < NB);

    // start the DRAM stream for layers 0 and 1 immediately
    prefetch_layer((const char*)S_mid, (const char*)theta_mid, 0, t);
    prefetch_layer((const char*)S_mid, (const char*)theta_mid, 1, t);

    if (lane == 0 && act) { g_inflow[0][b] = 0.0f; g_inflow[1][b] = 0.0f; }

    const float pre      = precip[0];
    const float p_layer  = pre * (1.0f / 16.0f);
    const float p_bucket = p_layer * (1.0f / 1024.0f);

    float bh[32], cc[32];
    float q0_mine = 0.0f;
    float unused;

    // init arrive: my zeros are L2-visible (fence+release); done before the
    // long head chain so the round-1 rendezvous hides under it.
    if (act) {
        __threadfence();
        if (lane == 0) red_add_rel(&g_ctr, 1u);
    }

    // redundant head-bucket solve (identical data+ops on every warp);
    // each warp extracts its own bucket's q0 from registers.
    {
        stage_regs((const float2*)S0, theta0, lane, bh, cc);
        float H0h = H0p[0];
        float He = bucket_chain<false, true>(lane, H0h, p_layer, bh, cc,
                                             nullptr, (b & 1023) >> 5, b & 31,
                                             q0_mine);
        if (blockIdx.x == 0 && w == 0 && lane == 0)
            out[0] = (2.0f * He - H0h) + p_layer;    // H0 - cum + inflow
    }

    // stage layer 0 (prefetched above -> mostly L2 hits)
    if (act)
        stage_regs((const float2*)S_mid + (size_t)b * NB,
                   theta_mid + (size_t)b * NB, lane, bh, cc);

    // round-1 rendezvous: all zeros visible before any layer-0 flush
    if (act && lane == 0)
        while (ld_acq(&g_ctr) < 1024u) { }
    __syncwarp();                                 // extend acquire to warp

    float inflow = q0_mine + p_bucket;            // layer-0 inflow from regs

    for (int l = 0; l < NM; ++l) {
        if (act) {
            // chain layer l; flush into buf[(l+1)&1]
            float H0 = H_mid[(size_t)l * NB + b];
            float He = bucket_chain<true, false>(lane, H0, inflow, bh, cc,
                                                 g_inflow[(l + 1) & 1], 0, 0,
                                                 unused);
            if (lane == 0) out[1 + l * NB + b] = (2.0f * He - H0) + inflow;
            // stage l+1 (L2 hits; loads fly during the rendezvous)
            if (l + 1 < NM) {
                size_t row = (size_t)(l + 1) * NB + (size_t)b;
                stage_regs((const float2*)S_mid + row * NB,
                           theta_mid + row * NB, lane, bh, cc);
            }
        }
        if (l + 2 < NM)
            prefetch_layer((const char*)S_mid, (const char*)theta_mid, l + 2, t);

        if (act) {
            __threadfence();                      // drain my flush REDs
            __syncwarp();                         // all lanes' REDs ordered
            unsigned v = 0u;
            if (lane == 0) {
                red_add_rel(&g_ctr, 1u);          // layer-l arrival
                unsigned tgt = 1024u * (unsigned)(l + 2);
                while (ld_acq(&g_ctr) < tgt) { }  // all layer-l flushes visible
                float* slot = &g_inflow[(l + 1) & 1][b];
                v = ld_acq((unsigned*)slot);      // acquire: bypass stale L1
                *slot = 0.0f;                     // recycle (ordered by next arrive)
            }
            inflow = __uint_as_float(__shfl_sync(0xFFFFFFFFu, v, 0)) + p_bucket;
        }
    }

    // last layer: one outlet spigot per bucket (inflow = final read above)
    if (act && lane == 0) {
        float H0 = H_last[b];
        float sh = S_last[2 * b + 0];
        float a  = S_last[2 * b + 1];
        float h  = fmaxf((H0 + inflow) - sh, 0.0f);
        float q  = theta_last[b] * sqrt_approx(19.6f * h) * a;
        out[1 + NM * NB + b]      = (H0 - q) + inflow;
        out[1 + NM * NB + NB + b] = q;
    }

    // reset counters for the next graph replay (last block to exit; all
    // other blocks have passed their final poll and no longer read g_ctr)
    __syncthreads();
    if (tid == 0) {
        __threadfence();
        unsigned vexit = atomicAdd(&g_exit, 1u);
        if (vexit == NBLK - 1) { g_ctr = 0u; g_exit = 0u; __threadfence(); }
    }
}

// ---------------------------------------------------------------------------
extern "C" void kernel_launch(void* const* d_in, const int* in_sizes, int n_in,
                              void* d_out, int out_size)
{
    const float* H0         = (const float*)d_in[0];
    const float* H_mid      = (const float*)d_in[1];
    const float* H_last     = (const float*)d_in[2];
    const float* S0         = (const float*)d_in[3];
    const float* S_mid      = (const float*)d_in[4];
    const float* S_last     = (const float*)d_in[5];
    const float* theta0     = (const float*)d_in[6];
    const float* theta_mid  = (const float*)d_in[7];
    const float* theta_last = (const float*)d_in[8];
    const float* precip     = (const float*)d_in[9];
    float* out = (float*)d_out;

    k_cascade<<<NBLK, NTHR>>>(H0, H_mid, H_last, S0, S_mid, S_last,
                              theta0, theta_mid, theta_last, precip, out);
}

// round 17
// speedup vs baseline: 1.4383x; 1.1305x over previous
#include <cuda_runtime.h>
#include <cuda_bf16.h>
#include <cstdint>
#include <cstddef>

#define NB   1024
#define NM   14
#define NBLK 148
#define WPB  7                  // warps (=buckets) per block
#define NTHR (WPB * 32)         // 224
#define NTOT (NBLK * NTHR)      // 33152

// Inflow ping-pong buffers + barrier state. Self-resetting per launch:
// zeros at start, consumer-zeroed per layer; g_ctr/g_exit reset by the
// last-exiting block so graph replays start clean.
__device__ float    g_inflow[2][NB];
__device__ unsigned g_ctr;
__device__ unsigned g_exit;

__device__ __forceinline__ float sqrt_approx(float x) {
    float y; asm("sqrt.approx.f32 %0, %1;" : "=f"(y) : "f"(x)); return y;
}
__device__ __forceinline__ unsigned ld_acq(const unsigned* p) {
    unsigned v; asm volatile("ld.acquire.gpu.global.u32 %0, [%1];" : "=r"(v) : "l"(p)); return v;
}
__device__ __forceinline__ void l2pf(const void* p) {
    asm volatile("prefetch.global.L2 [%0];" :: "l"(p));
}

// Split grid barrier (all 148 blocks resident, 1 block/SM), R13 semantics:
// arrive = syncthreads (all warps' REDs issued) + fence + atomicAdd;
// wait   = acquire-poll by thread0 + syncthreads.
// Anything placed between arrive and wait overlaps the rendezvous.
__device__ __forceinline__ void barrier_arrive() {
    __syncthreads();
    if (threadIdx.x == 0) {
        __threadfence();
        atomicAdd(&g_ctr, 1u);
    }
}
__device__ __forceinline__ void barrier_wait(unsigned target) {
    if (threadIdx.x == 0) {
        while (ld_acq(&g_ctr) < target) { }
    }
    __syncthreads();
}

// Prefetch one mid layer (8 MB S + 4 MB theta = 98304 x 128B lines) into L2.
__device__ __forceinline__ void prefetch_layer(const char* Sb, const char* Tb,
                                               int l, int t) {
    const char* S = Sb + (size_t)l * 8388608;
    const char* T = Tb + (size_t)l * 4194304;
    #pragma unroll
    for (int k = 0; k < 3; ++k) {
        long line = (long)t + (long)k * NTOT;
        if (line < 65536)       l2pf(S + line * 128);
        else if (line < 98304)  l2pf(T + (line - 65536) * 128);
    }
}

// Stage a bucket row into registers: lane holds spigots {w*32+lane}.
// NOTE: consumes its loads (cc multiply) -> always call between
// barrier_arrive and barrier_wait so the stall overlaps the rendezvous.
__device__ __forceinline__ void stage_regs(const float2* __restrict__ S2,
                                           const float* __restrict__ T,
                                           int lane, float bh[32], float cc[32]) {
    const float SQ2G = 4.4271887242357310f;   // sqrt(2*9.8)
    #pragma unroll
    for (int w = 0; w < 32; ++w) {
        float2 p = S2[w * 32 + lane];
        bh[w] = p.x; cc[w] = p.y;
    }
    #pragma unroll
    for (int w = 0; w < 32; ++w)
        cc[w] = cc[w] * T[w * 32 + lane] * SQ2G;
}

// Sequential recurrence, H_eff-only form (R13, unchanged). Exact: dry
// spigots give q==0 and leave H_eff bit-identical; lowest firing index
// first via ballot+ffs; windows drain in index order. Early-exit +
// eligibility bitmap are exact under monotone-decreasing H.
// Returns final H_eff; cum = 2*(H0 - H_eff_final).
template <bool ATOMIC, bool EXTRACT>
__device__ float bucket_chain(int lane, float H0, float inflow,
                              const float bh[32], const float cc[32],
                              float* __restrict__ nxt,
                              int wb, int lb, float& qsel)
{
    const unsigned FULL = 0xFFFFFFFFu;
    // spigot 0: H_eff = H0 + inflow (reference quirk)
    float bh0 = __shfl_sync(FULL, bh[0], 0);
    float cc0 = __shfl_sync(FULL, cc[0], 0);
    float h0  = fmaxf((H0 + inflow) - bh0, 0.0f);
    float q0  = cc0 * sqrt_approx(h0);
    float H_eff = fmaf(-0.5f, q0, H0);

    float qx = 0.0f;

    // ---- window 0: plain loop (the H plunge happens here) ----
    {
        float qacc = (lane == 0) ? q0 : 0.0f;
        unsigned rem = 0xFFFFFFFEu;                      // spigot 0 done
        while (true) {
            float h = H_eff - bh[0];
            unsigned fire = __ballot_sync(FULL, h > 0.0f) & rem;
            if (!fire) break;
            float q  = cc[0] * sqrt_approx(h);
            float Hc = fmaf(-0.5f, q, H_eff);
            int f = __ffs(fire) - 1;
            H_eff = __shfl_sync(FULL, Hc, f);
            qacc = (lane == f) ? q : qacc;
            rem &= (0xFFFFFFFEu << f);
            if (!(fire & rem)) break;                    // exact early exit
        }
        if (EXTRACT) {
            qx = (wb == 0) ? qacc : qx;
        } else if (qacc != 0.0f) {
            if (ATOMIC) atomicAdd(&nxt[lane], qacc);
            else        nxt[lane] = qacc;
        }
    }

    // ---- eligibility bitmap for windows 1..31 (pipelined ballots) ----
    unsigned elig = 0u;
    #pragma unroll
    for (int w = 1; w < 32; ++w) {
        unsigned m = __ballot_sync(FULL, H_eff > bh[w]);
        elig |= (m ? 1u : 0u) << w;
    }

    #pragma unroll
    for (int w = 1; w < 32; ++w) {
        if (!(elig & (1u << w))) continue;               // never-eligible: 2cy
        float qacc = 0.0f;
        unsigned rem = FULL;
        while (true) {
            float h = H_eff - bh[w];
            unsigned fire = __ballot_sync(FULL, h > 0.0f) & rem;
            if (!fire) break;
            float q  = cc[w] * sqrt_approx(h);
            float Hc = fmaf(-0.5f, q, H_eff);
            int f = __ffs(fire) - 1;
            H_eff = __shfl_sync(FULL, Hc, f);
            qacc = (lane == f) ? q : qacc;
            rem &= (0xFFFFFFFEu << f);
            if (!(fire & rem)) break;                    // exact early exit
        }
        if (EXTRACT) {
            qx = (w == wb) ? qacc : qx;
        } else if (qacc != 0.0f) {
            if (ATOMIC) atomicAdd(&nxt[w * 32 + lane], qacc);
            else        nxt[w * 32 + lane] = qacc;
        }
    }
    if (EXTRACT) qsel = __shfl_sync(FULL, qx, lb);
    return H_eff;
}

// ---------------------------------------------------------------------------
// Persistent kernel: 148 blocks x 224 threads, 1 block/SM, register-resident
// chains (R13 structure). The barrier is split: arrive right after the
// chains' REDs; staging (which stalls on L2 data) runs between arrive and
// wait, overlapping the rendezvous instead of delaying the arrival wave.
// ---------------------------------------------------------------------------
__global__ void __launch_bounds__(NTHR, 1)
k_cascade(const float* __restrict__ H0p,   const float* __restrict__ H_mid,
          const float* __restrict__ H_last,const float* __restrict__ S0,
          const float* __restrict__ S_mid, const float* __restrict__ S_last,
          const float* __restrict__ theta0,const float* __restrict__ theta_mid,
          const float* __restrict__ theta_last, const float* __restrict__ precip,
          float* __restrict__ out)
{
    const int tid  = threadIdx.x;
    const int lane = tid & 31;
    const int w    = tid >> 5;                    // 0..6
    const int b    = blockIdx.x * WPB + w;        // bucket id (may be >= NB)
    const int t    = blockIdx.x * NTHR + tid;     // linear thread id

    // start the DRAM stream for layers 0 and 1 immediately
    prefetch_layer((const char*)S_mid, (const char*)theta_mid, 0, t);
    prefetch_layer((const char*)S_mid, (const char*)theta_mid, 1, t);

    if (lane == 0 && b < NB) { g_inflow[0][b] = 0.0f; g_inflow[1][b] = 0.0f; }

    const float pre      = precip[0];
    const float p_layer  = pre * (1.0f / 16.0f);
    const float p_bucket = p_layer * (1.0f / 1024.0f);

    float bh[32], cc[32];
    float q0_mine = 0.0f;
    float unused;

    // phase 1 arrive immediately (zeros written above; syncthreads in
    // arrive orders all warps' zeros before thread0's fence+add)
    unsigned phase = 1;
    barrier_arrive();

    // head-bucket solve + layer-0 staging run during the rendezvous
    {
        stage_regs((const float2*)S0, theta0, lane, bh, cc);
        float H0h = H0p[0];
        float He = bucket_chain<false, true>(lane, H0h, p_layer, bh, cc,
                                             nullptr, (b & 1023) >> 5, b & 31,
                                             q0_mine);
        if (blockIdx.x == 0 && w == 0 && lane == 0)
            out[0] = (2.0f * He - H0h) + p_layer;    // H0 - cum + inflow
    }
    if (b < NB)
        stage_regs((const float2*)S_mid + (size_t)b * NB,
                   theta_mid + (size_t)b * NB, lane, bh, cc);

    barrier_wait(NBLK * phase); ++phase;          // inflow zeros visible

    float inflow = q0_mine + p_bucket;            // layer-0 inflow from regs

    for (int l = 0; l < NM; ++l) {
        // layer l chain; REDs into buf[(l+1)&1]
        if (b < NB) {
            float H0 = H_mid[(size_t)l * NB + b];
            float He = bucket_chain<true, false>(lane, H0, inflow, bh, cc,
                                                 g_inflow[(l + 1) & 1], 0, 0,
                                                 unused);
            if (lane == 0) out[1 + l * NB + b] = (2.0f * He - H0) + inflow;
        }

        barrier_arrive();                         // REDs fenced + counted

        // staging + prefetch overlap the rendezvous
        if (l + 1 < NM && b < NB) {
            size_t row = (size_t)(l + 1) * NB + (size_t)b;
            stage_regs((const float2*)S_mid + row * NB,
                       theta_mid + row * NB, lane, bh, cc);
        }
        if (l + 2 < NM)
            prefetch_layer((const char*)S_mid, (const char*)theta_mid, l + 2, t);

        barrier_wait(NBLK * phase); ++phase;      // layer-l atomics visible

        // read next inflow (published by the barrier), zero slot for reuse
        if (l + 1 < NM && b < NB) {
            float inf0 = 0.0f;
            if (lane == 0) {
                inf0 = g_inflow[(l + 1) & 1][b];
                g_inflow[(l + 1) & 1][b] = 0.0f;
            }
            inflow = __shfl_sync(0xFFFFFFFFu, inf0, 0) + p_bucket;
        }
    }

    // last layer: one outlet spigot per bucket; layer 13 wrote buf[0]
    if (b < NB && lane == 0) {
        float inflowL = g_inflow[0][b] + p_bucket;
        float H0 = H_last[b];
        float sh = S_last[2 * b + 0];
        float a  = S_last[2 * b + 1];
        float h  = fmaxf((H0 + inflowL) - sh, 0.0f);
        float q  = theta_last[b] * sqrt_approx(19.6f * h) * a;
        out[1 + NM * NB + b]      = (H0 - q) + inflowL;
        out[1 + NM * NB + NB + b] = q;
    }

    // reset barrier state for the next graph replay (last block to exit;
    // all other blocks have passed their final barrier and no longer read it)
    __syncthreads();
    if (tid == 0) {
        __threadfence();
        unsigned v = atomicAdd(&g_exit, 1u);
        if (v == NBLK - 1) { g_ctr = 0u; g_exit = 0u; __threadfence(); }
    }
}

// ---------------------------------------------------------------------------
extern "C" void kernel_launch(void* const* d_in, const int* in_sizes, int n_in,
                              void* d_out, int out_size)
{
    const float* H0         = (const float*)d_in[0];
    const float* H_mid      = (const float*)d_in[1];
    const float* H_last     = (const float*)d_in[2];
    const float* S0         = (const float*)d_in[3];
    const float* S_mid      = (const float*)d_in[4];
    const float* S_last     = (const float*)d_in[5];
    const float* theta0     = (const float*)d_in[6];
    const float* theta_mid  = (const float*)d_in[7];
    const float* theta_last = (const float*)d_in[8];
    const float* precip     = (const float*)d_in[9];
    float* out = (float*)d_out;

    k_cascade<<<NBLK, NTHR>>>(H0, H_mid, H_last, S0, S_mid, S_last,
                              theta0, theta_mid, theta_last, precip, out);
}